// round 12
// baseline (speedup 1.0000x reference)
#include <cuda_runtime.h>
#include <cuda_fp16.h>
#include <cstdint>

#define NN 100000
#define EP 1000000
#define EN 500000
#define NBLK ((NN + 1023) / 1024)   // 98

// ---------------- scratch (device globals: no allocations allowed) ----------
__device__ __align__(256) float  g_aggA[NN * 64];  // agg sums; layer2 reuses as z2
__device__ __align__(256) float  g_aggB[NN * 64];
__device__ __align__(256) __half g_xh[NN * 64];    // fp16 copy of x
__device__ __align__(256) __half g_zh[NN * 64];    // fp16 layer1 output
__device__ __align__(256) float  g_dpos[NN];
__device__ __align__(256) float  g_dneg[NN];
// CSR build
__device__ __align__(256) int  g_pcnt[NN];
__device__ __align__(256) int  g_ncnt[NN];
__device__ __align__(256) int  g_poff[NN + 1];
__device__ __align__(256) int  g_noff[NN + 1];
__device__ __align__(256) int  g_prank[EP];
__device__ __align__(256) int  g_nrank[EN];
__device__ __align__(256) int  g_blksum[2][NBLK];
__device__ __align__(256) int2 g_pedge[EP];        // (src, bitcast weight) in dst order
__device__ __align__(256) int2 g_nedge[EN];

// ---------------- helpers ----------------------------------------------------
__device__ __forceinline__ float tanha(float x) {
    float r;
    asm("tanh.approx.f32 %0, %1;" : "=f"(r) : "f"(x));
    return r;
}

// ---------------- x -> fp16 --------------------------------------------------
__global__ void convx_kernel(const float4* __restrict__ x4) {
    int i = blockIdx.x * blockDim.x + threadIdx.x;
    if (i >= NN * 16) return;
    float4 v = x4[i];
    __half2 h0 = __floats2half2_rn(v.x, v.y);
    __half2 h1 = __floats2half2_rn(v.z, v.w);
    uint2 u;
    u.x = *reinterpret_cast<const unsigned*>(&h0);
    u.y = *reinterpret_cast<const unsigned*>(&h1);
    reinterpret_cast<uint2*>(g_xh)[i] = u;
}

// ---------------- CSR build --------------------------------------------------
__global__ void zero_cnt_kernel() {
    int i = blockIdx.x * blockDim.x + threadIdx.x;
    if (i < NN) {
        g_pcnt[i] = 0;
        g_ncnt[i] = 0;
    }
}

__global__ void hist_kernel(const int* __restrict__ pei, const int* __restrict__ nei) {
    int t = blockIdx.x * blockDim.x + threadIdx.x;
    if (t < EP) {
        int d = pei[EP + t];
        g_prank[t] = atomicAdd(&g_pcnt[d], 1);
    } else if (t < EP + EN) {
        int e = t - EP;
        int d = nei[EN + e];
        g_nrank[e] = atomicAdd(&g_ncnt[d], 1);
    }
}

// Phase 1: per-block exclusive scan; block totals to g_blksum.
__global__ void scan1_kernel() {
    __shared__ int swsum[32];
    int arr = blockIdx.y;
    const int* cnt = arr ? g_ncnt : g_pcnt;
    int* off = arr ? g_noff : g_poff;
    int tid = threadIdx.x, lane = tid & 31, wid = tid >> 5;
    int i = blockIdx.x * 1024 + tid;
    int v = (i < NN) ? cnt[i] : 0;
    int val = v;
#pragma unroll
    for (int o = 1; o < 32; o <<= 1) {
        int t2 = __shfl_up_sync(0xFFFFFFFFu, val, o);
        if (lane >= o) val += t2;
    }
    if (lane == 31) swsum[wid] = val;
    __syncthreads();
    if (wid == 0) {
        int s = swsum[lane];
#pragma unroll
        for (int o = 1; o < 32; o <<= 1) {
            int t2 = __shfl_up_sync(0xFFFFFFFFu, s, o);
            if (lane >= o) s += t2;
        }
        swsum[lane] = s;
    }
    __syncthreads();
    int woff = wid ? swsum[wid - 1] : 0;
    int incl = val + woff;
    if (i < NN) off[i] = incl - v;
    if (tid == 1023) g_blksum[arr][blockIdx.x] = incl;
}

// Phase 2 (merged): each block reduces blksum[0..bx-1] and adds it.
__global__ void scan3_kernel() {
    __shared__ int s_pref;
    int arr = blockIdx.y;
    int* off = arr ? g_noff : g_poff;
    int bx = blockIdx.x;
    if (threadIdx.x < 32) {
        int lane = threadIdx.x;
        int acc = 0;
        for (int idx = lane; idx < bx; idx += 32) acc += g_blksum[arr][idx];
#pragma unroll
        for (int o = 16; o; o >>= 1) acc += __shfl_xor_sync(0xFFFFFFFFu, acc, o);
        if (lane == 0) s_pref = acc;
    }
    __syncthreads();
    int pref = s_pref;
    int i = bx * 1024 + threadIdx.x;
    if (i < NN) off[i] += pref;
    if (bx == NBLK - 1 && threadIdx.x == 0)
        off[NN] = pref + g_blksum[arr][NBLK - 1];
}

// Fill CSR edge arrays — no atomics (slot = off[dst] + precomputed rank).
__global__ void fill_kernel(const int* __restrict__ pei, const int* __restrict__ nei,
                            const float* __restrict__ pw, const float* __restrict__ nw) {
    int t = blockIdx.x * blockDim.x + threadIdx.x;
    if (t < EP) {
        int dst = pei[EP + t];
        g_pedge[g_poff[dst] + g_prank[t]] = make_int2(pei[t], __float_as_int(pw[t]));
    } else if (t < EP + EN) {
        int e = t - EP;
        int dst = nei[EN + e];
        g_nedge[g_noff[dst] + g_nrank[e]] = make_int2(nei[e], __float_as_int(nw[e]));
    }
}

// ---------------- CSR gather: one warp per node ------------------------------
// 32 lanes = 16 chunks (c) x 2 edge-list halves (h). Each half walks half of
// the node's edges; partials combine via shfl_xor(16).
// use_z: 0 -> g_xh, 1 -> g_zh.  swap: neg side reads chunk c^8.
// dosum: lane 0 stores per-node weight sums (first gather only).
__device__ __forceinline__ void h4acc(uint2 r, float w, float4& acc) {
    __half2 ha = *reinterpret_cast<__half2*>(&r.x);
    __half2 hb = *reinterpret_cast<__half2*>(&r.y);
    float2 fa = __half22float2(ha);
    float2 fb = __half22float2(hb);
    acc.x += w * fa.x; acc.y += w * fa.y;
    acc.z += w * fb.x; acc.w += w * fb.y;
}

__device__ __forceinline__ void gather_list(const int2* __restrict__ edge,
                                            const uint2* __restrict__ feat,
                                            int lo, int hi, int c,
                                            float4& acc, float& wsum) {
    int i = lo;
    for (; i + 4 <= hi; i += 4) {
        int2 e0 = edge[i + 0];
        int2 e1 = edge[i + 1];
        int2 e2 = edge[i + 2];
        int2 e3 = edge[i + 3];
        uint2 r0 = __ldg(&feat[(size_t)e0.x * 16 + c]);
        uint2 r1 = __ldg(&feat[(size_t)e1.x * 16 + c]);
        uint2 r2 = __ldg(&feat[(size_t)e2.x * 16 + c]);
        uint2 r3 = __ldg(&feat[(size_t)e3.x * 16 + c]);
        float w0 = __int_as_float(e0.y), w1 = __int_as_float(e1.y);
        float w2 = __int_as_float(e2.y), w3 = __int_as_float(e3.y);
        wsum += w0 + w1 + w2 + w3;
        h4acc(r0, w0, acc);
        h4acc(r1, w1, acc);
        h4acc(r2, w2, acc);
        h4acc(r3, w3, acc);
    }
    for (; i < hi; i++) {
        int2 ed = edge[i];
        float w = __int_as_float(ed.y);
        uint2 r = __ldg(&feat[(size_t)ed.x * 16 + c]);
        wsum += w;
        h4acc(r, w, acc);
    }
}

__global__ void gather_kernel(int use_z, int swap, int dosum) {
    int t = blockIdx.x * blockDim.x + threadIdx.x;
    int n = t >> 5;
    if (n >= NN) return;
    int lane = t & 31;
    int c = lane & 15;
    int h = lane >> 4;
    const uint2* feat = use_z ? reinterpret_cast<const uint2*>(g_zh)
                              : reinterpret_cast<const uint2*>(g_xh);

    // pos list, split in two halves across h
    float4 accA = make_float4(0.f, 0.f, 0.f, 0.f);
    float wsumA = 0.f;
    {
        int b = g_poff[n], e = g_poff[n + 1];
        int mid = b + ((e - b + 1) >> 1);
        int lo = h ? mid : b;
        int hi = h ? e : mid;
        gather_list(g_pedge, feat, lo, hi, c, accA, wsumA);
    }

    int sc = c ^ (swap << 3);
    float4 accB = make_float4(0.f, 0.f, 0.f, 0.f);
    float wsumB = 0.f;
    {
        int b = g_noff[n], e = g_noff[n + 1];
        int mid = b + ((e - b + 1) >> 1);
        int lo = h ? mid : b;
        int hi = h ? e : mid;
        gather_list(g_nedge, feat, lo, hi, sc, accB, wsumB);
    }

    // combine the two halves (lane and lane^16 hold partials of same chunk)
    const unsigned FULL = 0xFFFFFFFFu;
    accA.x += __shfl_xor_sync(FULL, accA.x, 16);
    accA.y += __shfl_xor_sync(FULL, accA.y, 16);
    accA.z += __shfl_xor_sync(FULL, accA.z, 16);
    accA.w += __shfl_xor_sync(FULL, accA.w, 16);
    accB.x += __shfl_xor_sync(FULL, accB.x, 16);
    accB.y += __shfl_xor_sync(FULL, accB.y, 16);
    accB.z += __shfl_xor_sync(FULL, accB.z, 16);
    accB.w += __shfl_xor_sync(FULL, accB.w, 16);
    wsumA += __shfl_xor_sync(FULL, wsumA, 16);
    wsumB += __shfl_xor_sync(FULL, wsumB, 16);

    if (h == 0) {
        reinterpret_cast<float4*>(g_aggA)[n * 16 + c] = accA;
        reinterpret_cast<float4*>(g_aggB)[n * 16 + c] = accB;
        if (dosum && c == 0) {
            g_dpos[n] = wsumA;
            g_dneg[n] = wsumB;
        }
    }
}

// ---------------- layer 1: z = tanh([ap,x]@w1p+b1p | [an,x]@w1n+b1n) ---------
// Writes z as fp16 into g_zh.
__global__ __launch_bounds__(128) void layer1_kernel(
    const float4* __restrict__ x4,
    const float* __restrict__ w1p, const float* __restrict__ b1p,
    const float* __restrict__ w1n, const float* __restrict__ b1n) {
    __shared__ float sWp[128 * 32];
    __shared__ float sWn[128 * 32];
    for (int i = threadIdx.x; i < 128 * 32; i += 128) {
        sWp[i] = w1p[i];
        sWn[i] = w1n[i];
    }
    __syncthreads();

    int n = blockIdx.x * 128 + threadIdx.x;
    if (n >= NN) return;

    float invp = 1.f / fmaxf(g_dpos[n], 1e-12f);
    float invn = 1.f / fmaxf(g_dneg[n], 1e-12f);

    float aP[32], aN[32];
#pragma unroll
    for (int j = 0; j < 32; j++) { aP[j] = b1p[j]; aN[j] = b1n[j]; }

    const float4* rA = reinterpret_cast<const float4*>(g_aggA) + n * 16;
    const float4* rB = reinterpret_cast<const float4*>(g_aggB) + n * 16;
    const float4* rX = x4 + n * 16;

#pragma unroll 1
    for (int k4 = 0; k4 < 16; k4++) {
        float4 a = rA[k4];
        float4 b = rB[k4];
        float4 xv = rX[k4];
        float av[4] = { a.x * invp, a.y * invp, a.z * invp, a.w * invp };
        float bv[4] = { b.x * invn, b.y * invn, b.z * invn, b.w * invn };
        float xe[4] = { xv.x, xv.y, xv.z, xv.w };
#pragma unroll
        for (int kk = 0; kk < 4; kk++) {
            int k = k4 * 4 + kk;
            const float4* wpA = reinterpret_cast<const float4*>(sWp + k * 32);
            const float4* wpX = reinterpret_cast<const float4*>(sWp + (64 + k) * 32);
            const float4* wnA = reinterpret_cast<const float4*>(sWn + k * 32);
            const float4* wnX = reinterpret_cast<const float4*>(sWn + (64 + k) * 32);
#pragma unroll
            for (int j4 = 0; j4 < 8; j4++) {
                float4 wp = wpA[j4];
                float4 wx = wpX[j4];
                float4 wn = wnA[j4];
                float4 wq = wnX[j4];
                aP[4 * j4 + 0] += av[kk] * wp.x + xe[kk] * wx.x;
                aP[4 * j4 + 1] += av[kk] * wp.y + xe[kk] * wx.y;
                aP[4 * j4 + 2] += av[kk] * wp.z + xe[kk] * wx.z;
                aP[4 * j4 + 3] += av[kk] * wp.w + xe[kk] * wx.w;
                aN[4 * j4 + 0] += bv[kk] * wn.x + xe[kk] * wq.x;
                aN[4 * j4 + 1] += bv[kk] * wn.y + xe[kk] * wq.y;
                aN[4 * j4 + 2] += bv[kk] * wn.z + xe[kk] * wq.z;
                aN[4 * j4 + 3] += bv[kk] * wn.w + xe[kk] * wq.w;
            }
        }
    }

    // z row = [zp(32) | zn(32)] halfs
    __half2* zr = reinterpret_cast<__half2*>(g_zh + (size_t)n * 64);
#pragma unroll
    for (int t2 = 0; t2 < 16; t2++) {
        zr[t2] = __floats2half2_rn(tanha(aP[2 * t2]), tanha(aP[2 * t2 + 1]));
        zr[16 + t2] = __floats2half2_rn(tanha(aN[2 * t2]), tanha(aN[2 * t2 + 1]));
    }
}

// ---------------- layer 2 ----------------------------------------------------
// Reads z fp16; writes z2 fp32 in-place into g_aggA (row-private).
__global__ __launch_bounds__(128) void layer2_kernel(
    const float* __restrict__ w2p, const float* __restrict__ b2p,
    const float* __restrict__ w2n, const float* __restrict__ b2n) {
    __shared__ float sP[96 * 32];
    __shared__ float sN[96 * 32];
    for (int i = threadIdx.x; i < 96 * 32; i += 128) {
        sP[i] = w2p[i];
        sN[i] = w2n[i];
    }
    __syncthreads();

    int n = blockIdx.x * 128 + threadIdx.x;
    if (n >= NN) return;

    float invp = 1.f / fmaxf(g_dpos[n], 1e-12f);
    float invn = 1.f / fmaxf(g_dneg[n], 1e-12f);

    float aP[32], aN[32];
#pragma unroll
    for (int j = 0; j < 32; j++) { aP[j] = b2p[j]; aN[j] = b2n[j]; }

    const float4* rA = reinterpret_cast<const float4*>(g_aggA) + n * 16;
    const float4* rB = reinterpret_cast<const float4*>(g_aggB) + n * 16;
    const uint2*  rZ = reinterpret_cast<const uint2*>(g_zh) + n * 16;

#pragma unroll 1
    for (int k4 = 0; k4 < 8; k4++) {
        float4 A1 = rA[k4];
        float4 A3 = rA[8 + k4];
        float4 A2 = rB[k4];
        float4 A4 = rB[8 + k4];
        uint2 zpu = rZ[k4];
        uint2 znu = rZ[8 + k4];
        float2 zp0 = __half22float2(*reinterpret_cast<__half2*>(&zpu.x));
        float2 zp1 = __half22float2(*reinterpret_cast<__half2*>(&zpu.y));
        float2 zn0 = __half22float2(*reinterpret_cast<__half2*>(&znu.x));
        float2 zn1 = __half22float2(*reinterpret_cast<__half2*>(&znu.y));
        float a1[4] = { A1.x * invp, A1.y * invp, A1.z * invp, A1.w * invp };
        float a3[4] = { A3.x * invp, A3.y * invp, A3.z * invp, A3.w * invp };
        float a2[4] = { A2.x * invn, A2.y * invn, A2.z * invn, A2.w * invn };
        float a4[4] = { A4.x * invn, A4.y * invn, A4.z * invn, A4.w * invn };
        float zpv[4] = { zp0.x, zp0.y, zp1.x, zp1.y };
        float znv[4] = { zn0.x, zn0.y, zn1.x, zn1.y };
#pragma unroll
        for (int kk = 0; kk < 4; kk++) {
            int k = k4 * 4 + kk;
            const float4* p0 = reinterpret_cast<const float4*>(sP + k * 32);
            const float4* p1 = reinterpret_cast<const float4*>(sP + (32 + k) * 32);
            const float4* p2 = reinterpret_cast<const float4*>(sP + (64 + k) * 32);
            const float4* q0 = reinterpret_cast<const float4*>(sN + k * 32);
            const float4* q1 = reinterpret_cast<const float4*>(sN + (32 + k) * 32);
            const float4* q2 = reinterpret_cast<const float4*>(sN + (64 + k) * 32);
#pragma unroll
            for (int j4 = 0; j4 < 8; j4++) {
                float4 w0 = p0[j4], w1 = p1[j4], w2 = p2[j4];
                aP[4 * j4 + 0] += a1[kk] * w0.x + a2[kk] * w1.x + zpv[kk] * w2.x;
                aP[4 * j4 + 1] += a1[kk] * w0.y + a2[kk] * w1.y + zpv[kk] * w2.y;
                aP[4 * j4 + 2] += a1[kk] * w0.z + a2[kk] * w1.z + zpv[kk] * w2.z;
                aP[4 * j4 + 3] += a1[kk] * w0.w + a2[kk] * w1.w + zpv[kk] * w2.w;
                float4 v0 = q0[j4], v1 = q1[j4], v2 = q2[j4];
                aN[4 * j4 + 0] += a3[kk] * v0.x + a4[kk] * v1.x + znv[kk] * v2.x;
                aN[4 * j4 + 1] += a3[kk] * v0.y + a4[kk] * v1.y + znv[kk] * v2.y;
                aN[4 * j4 + 2] += a3[kk] * v0.z + a4[kk] * v1.z + znv[kk] * v2.z;
                aN[4 * j4 + 3] += a3[kk] * v0.w + a4[kk] * v1.w + znv[kk] * v2.w;
            }
        }
    }

    // z2 (fp32) in-place into g_aggA row n (this thread's private row)
    float4* zr = reinterpret_cast<float4*>(g_aggA) + n * 16;
#pragma unroll
    for (int j4 = 0; j4 < 8; j4++) {
        zr[j4] = make_float4(tanha(aP[4 * j4 + 0]), tanha(aP[4 * j4 + 1]),
                             tanha(aP[4 * j4 + 2]), tanha(aP[4 * j4 + 3]));
        zr[8 + j4] = make_float4(tanha(aN[4 * j4 + 0]), tanha(aN[4 * j4 + 1]),
                                 tanha(aN[4 * j4 + 2]), tanha(aN[4 * j4 + 3]));
    }
}

// ---------------- layer 3: out = tanh(z2 @ wout + bout) ----------------------
__global__ __launch_bounds__(128) void layer3_kernel(
    const float* __restrict__ wout, const float* __restrict__ bout,
    float* __restrict__ out) {
    __shared__ float sO[64 * 64];
    for (int i = threadIdx.x; i < 64 * 64; i += 128) sO[i] = wout[i];
    __syncthreads();

    int n = blockIdx.x * 128 + threadIdx.x;
    if (n >= NN) return;

    float o[64];
#pragma unroll
    for (int j = 0; j < 64; j++) o[j] = bout[j];

    const float4* rz = reinterpret_cast<const float4*>(g_aggA) + n * 16;
#pragma unroll 1
    for (int k4 = 0; k4 < 16; k4++) {
        float4 zc = rz[k4];
        float zv[4] = { zc.x, zc.y, zc.z, zc.w };
#pragma unroll
        for (int kk = 0; kk < 4; kk++) {
            const float4* wr = reinterpret_cast<const float4*>(sO + (k4 * 4 + kk) * 64);
#pragma unroll
            for (int j4 = 0; j4 < 16; j4++) {
                float4 w = wr[j4];
                o[4 * j4 + 0] += zv[kk] * w.x;
                o[4 * j4 + 1] += zv[kk] * w.y;
                o[4 * j4 + 2] += zv[kk] * w.z;
                o[4 * j4 + 3] += zv[kk] * w.w;
            }
        }
    }

    float4* orow = reinterpret_cast<float4*>(out + (size_t)n * 64);
#pragma unroll
    for (int j4 = 0; j4 < 16; j4++) {
        orow[j4] = make_float4(tanha(o[4 * j4 + 0]), tanha(o[4 * j4 + 1]),
                               tanha(o[4 * j4 + 2]), tanha(o[4 * j4 + 3]));
    }
}

// ---------------- launch -----------------------------------------------------
extern "C" void kernel_launch(void* const* d_in, const int* in_sizes, int n_in,
                              void* d_out, int out_size) {
    const int*   pei  = (const int*)d_in[0];
    const int*   nei  = (const int*)d_in[1];
    const float* pw   = (const float*)d_in[2];
    const float* nw   = (const float*)d_in[3];
    const float* x    = (const float*)d_in[4];
    const float* w1p  = (const float*)d_in[5];
    const float* b1p  = (const float*)d_in[6];
    const float* w1n  = (const float*)d_in[7];
    const float* b1n  = (const float*)d_in[8];
    const float* w2p  = (const float*)d_in[9];
    const float* b2p  = (const float*)d_in[10];
    const float* w2n  = (const float*)d_in[11];
    const float* b2n  = (const float*)d_in[12];
    const float* wout = (const float*)d_in[13];
    const float* bout = (const float*)d_in[14];
    float* out = (float*)d_out;

    const int EB = (EP + EN + 255) / 256;
    const int GB = (NN * 32 + 255) / 256;
    const int LB = (NN + 127) / 128;

    // fp16 feature table + CSR build
    convx_kernel<<<(NN * 16 + 255) / 256, 256>>>((const float4*)x);
    zero_cnt_kernel<<<(NN + 255) / 256, 256>>>();
    hist_kernel<<<EB, 256>>>(pei, nei);
    scan1_kernel<<<dim3(NBLK, 2), 1024>>>();
    scan3_kernel<<<dim3(NBLK, 2), 1024>>>();
    fill_kernel<<<EB, 256>>>(pei, nei, pw, nw);

    // Layer 1 (gather also computes the per-node weight sums)
    gather_kernel<<<GB, 256>>>(0, 0, 1);
    layer1_kernel<<<LB, 128>>>((const float4*)x, w1p, b1p, w1n, b1n);

    // Layer 2 (neg side swaps zp/zn halves in the gather), then layer 3
    gather_kernel<<<GB, 256>>>(1, 1, 0);
    layer2_kernel<<<LB, 128>>>(w2p, b2p, w2n, b2n);
    layer3_kernel<<<LB, 128>>>(wout, bout, out);

    (void)in_sizes; (void)n_in; (void)out_size;
}

// round 13
// speedup vs baseline: 1.0850x; 1.0850x over previous
#include <cuda_runtime.h>
#include <cuda_fp16.h>
#include <cstdint>

#define NN 100000
#define EP 1000000
#define EN 500000
#define NBLK ((NN + 1023) / 1024)   // 98

// ---------------- scratch (device globals: no allocations allowed) ----------
__device__ __align__(256) float  g_aggA[NN * 64];  // agg sums; layer2 reuses as z2
__device__ __align__(256) float  g_aggB[NN * 64];
__device__ __align__(256) __half g_xh[NN * 64];    // fp16 copy of x
__device__ __align__(256) __half g_zh[NN * 64];    // fp16 layer1 output
__device__ __align__(256) float  g_dpos[NN];
__device__ __align__(256) float  g_dneg[NN];
// CSR build
__device__ __align__(256) int  g_pcnt[NN];
__device__ __align__(256) int  g_ncnt[NN];
__device__ __align__(256) int  g_poff[NN + 1];
__device__ __align__(256) int  g_noff[NN + 1];
__device__ __align__(256) int  g_prank[EP];
__device__ __align__(256) int  g_nrank[EN];
__device__ __align__(256) int  g_blksum[2][NBLK];
__device__ __align__(256) int2 g_pedge[EP];        // (src, bitcast weight) in dst order
__device__ __align__(256) int2 g_nedge[EN];

// ---------------- helpers ----------------------------------------------------
__device__ __forceinline__ float tanha(float x) {
    float r;
    asm("tanh.approx.f32 %0, %1;" : "=f"(r) : "f"(x));
    return r;
}

// ---------------- x -> fp16 + zero counters (merged: keeps launch count at 5
// before the first gather so ncu -s 5 profiles gather #1 directly) -----------
__global__ void prep_kernel(const float4* __restrict__ x4) {
    int i = blockIdx.x * blockDim.x + threadIdx.x;
    if (i < NN * 16) {
        float4 v = x4[i];
        __half2 h0 = __floats2half2_rn(v.x, v.y);
        __half2 h1 = __floats2half2_rn(v.z, v.w);
        uint2 u;
        u.x = *reinterpret_cast<const unsigned*>(&h0);
        u.y = *reinterpret_cast<const unsigned*>(&h1);
        reinterpret_cast<uint2*>(g_xh)[i] = u;
    }
    if (i < NN) {
        g_pcnt[i] = 0;
        g_ncnt[i] = 0;
    }
}

// ---------------- CSR build --------------------------------------------------
__global__ void hist_kernel(const int* __restrict__ pei, const int* __restrict__ nei) {
    int t = blockIdx.x * blockDim.x + threadIdx.x;
    if (t < EP) {
        int d = pei[EP + t];
        g_prank[t] = atomicAdd(&g_pcnt[d], 1);
    } else if (t < EP + EN) {
        int e = t - EP;
        int d = nei[EN + e];
        g_nrank[e] = atomicAdd(&g_ncnt[d], 1);
    }
}

// Phase 1: per-block exclusive scan; block totals to g_blksum.
__global__ void scan1_kernel() {
    __shared__ int swsum[32];
    int arr = blockIdx.y;
    const int* cnt = arr ? g_ncnt : g_pcnt;
    int* off = arr ? g_noff : g_poff;
    int tid = threadIdx.x, lane = tid & 31, wid = tid >> 5;
    int i = blockIdx.x * 1024 + tid;
    int v = (i < NN) ? cnt[i] : 0;
    int val = v;
#pragma unroll
    for (int o = 1; o < 32; o <<= 1) {
        int t2 = __shfl_up_sync(0xFFFFFFFFu, val, o);
        if (lane >= o) val += t2;
    }
    if (lane == 31) swsum[wid] = val;
    __syncthreads();
    if (wid == 0) {
        int s = swsum[lane];
#pragma unroll
        for (int o = 1; o < 32; o <<= 1) {
            int t2 = __shfl_up_sync(0xFFFFFFFFu, s, o);
            if (lane >= o) s += t2;
        }
        swsum[lane] = s;
    }
    __syncthreads();
    int woff = wid ? swsum[wid - 1] : 0;
    int incl = val + woff;
    if (i < NN) off[i] = incl - v;
    if (tid == 1023) g_blksum[arr][blockIdx.x] = incl;
}

// Phase 2 (merged): each block reduces blksum[0..bx-1] and adds it.
__global__ void scan3_kernel() {
    __shared__ int s_pref;
    int arr = blockIdx.y;
    int* off = arr ? g_noff : g_poff;
    int bx = blockIdx.x;
    if (threadIdx.x < 32) {
        int lane = threadIdx.x;
        int acc = 0;
        for (int idx = lane; idx < bx; idx += 32) acc += g_blksum[arr][idx];
#pragma unroll
        for (int o = 16; o; o >>= 1) acc += __shfl_xor_sync(0xFFFFFFFFu, acc, o);
        if (lane == 0) s_pref = acc;
    }
    __syncthreads();
    int pref = s_pref;
    int i = bx * 1024 + threadIdx.x;
    if (i < NN) off[i] += pref;
    if (bx == NBLK - 1 && threadIdx.x == 0)
        off[NN] = pref + g_blksum[arr][NBLK - 1];
}

// Fill CSR edge arrays — no atomics (slot = off[dst] + precomputed rank).
__global__ void fill_kernel(const int* __restrict__ pei, const int* __restrict__ nei,
                            const float* __restrict__ pw, const float* __restrict__ nw) {
    int t = blockIdx.x * blockDim.x + threadIdx.x;
    if (t < EP) {
        int dst = pei[EP + t];
        g_pedge[g_poff[dst] + g_prank[t]] = make_int2(pei[t], __float_as_int(pw[t]));
    } else if (t < EP + EN) {
        int e = t - EP;
        int dst = nei[EN + e];
        g_nedge[g_noff[dst] + g_nrank[e]] = make_int2(nei[e], __float_as_int(nw[e]));
    }
}

// ---------------- CSR gather over fp16 features ------------------------------
// 16 threads per node; thread c owns 4 halfs (8 B) of the 64-half row.
// use_z: 0 -> g_xh, 1 -> g_zh.  swap: neg side reads chunk c^8.
// dosum: thread c==0 stores per-node weight sums (first gather only).
__device__ __forceinline__ void h4acc(uint2 r, float w, float4& acc) {
    __half2 ha = *reinterpret_cast<__half2*>(&r.x);
    __half2 hb = *reinterpret_cast<__half2*>(&r.y);
    float2 fa = __half22float2(ha);
    float2 fb = __half22float2(hb);
    acc.x += w * fa.x; acc.y += w * fa.y;
    acc.z += w * fb.x; acc.w += w * fb.y;
}

__global__ void gather_kernel(int use_z, int swap, int dosum) {
    int t = blockIdx.x * blockDim.x + threadIdx.x;
    int n = t >> 4;
    if (n >= NN) return;
    int c = t & 15;
    const uint2* feat = use_z ? reinterpret_cast<const uint2*>(g_zh)
                              : reinterpret_cast<const uint2*>(g_xh);

    float4 accA = make_float4(0.f, 0.f, 0.f, 0.f);
    float wsumA = 0.f;
    {
        int b = g_poff[n], e = g_poff[n + 1];
        int i = b;
        for (; i + 4 <= e; i += 4) {
            int2 e0 = g_pedge[i + 0];
            int2 e1 = g_pedge[i + 1];
            int2 e2 = g_pedge[i + 2];
            int2 e3 = g_pedge[i + 3];
            uint2 r0 = __ldg(&feat[(size_t)e0.x * 16 + c]);
            uint2 r1 = __ldg(&feat[(size_t)e1.x * 16 + c]);
            uint2 r2 = __ldg(&feat[(size_t)e2.x * 16 + c]);
            uint2 r3 = __ldg(&feat[(size_t)e3.x * 16 + c]);
            float w0 = __int_as_float(e0.y), w1 = __int_as_float(e1.y);
            float w2 = __int_as_float(e2.y), w3 = __int_as_float(e3.y);
            wsumA += w0 + w1 + w2 + w3;
            h4acc(r0, w0, accA);
            h4acc(r1, w1, accA);
            h4acc(r2, w2, accA);
            h4acc(r3, w3, accA);
        }
        for (; i < e; i++) {
            int2 ed = g_pedge[i];
            float w = __int_as_float(ed.y);
            uint2 r = __ldg(&feat[(size_t)ed.x * 16 + c]);
            wsumA += w;
            h4acc(r, w, accA);
        }
    }

    int sc = c ^ (swap << 3);
    float4 accB = make_float4(0.f, 0.f, 0.f, 0.f);
    float wsumB = 0.f;
    {
        int b = g_noff[n], e = g_noff[n + 1];
        int i = b;
        for (; i + 4 <= e; i += 4) {
            int2 e0 = g_nedge[i + 0];
            int2 e1 = g_nedge[i + 1];
            int2 e2 = g_nedge[i + 2];
            int2 e3 = g_nedge[i + 3];
            uint2 r0 = __ldg(&feat[(size_t)e0.x * 16 + sc]);
            uint2 r1 = __ldg(&feat[(size_t)e1.x * 16 + sc]);
            uint2 r2 = __ldg(&feat[(size_t)e2.x * 16 + sc]);
            uint2 r3 = __ldg(&feat[(size_t)e3.x * 16 + sc]);
            float w0 = __int_as_float(e0.y), w1 = __int_as_float(e1.y);
            float w2 = __int_as_float(e2.y), w3 = __int_as_float(e3.y);
            wsumB += w0 + w1 + w2 + w3;
            h4acc(r0, w0, accB);
            h4acc(r1, w1, accB);
            h4acc(r2, w2, accB);
            h4acc(r3, w3, accB);
        }
        for (; i < e; i++) {
            int2 ed = g_nedge[i];
            float w = __int_as_float(ed.y);
            uint2 r = __ldg(&feat[(size_t)ed.x * 16 + sc]);
            wsumB += w;
            h4acc(r, w, accB);
        }
    }

    reinterpret_cast<float4*>(g_aggA)[n * 16 + c] = accA;
    reinterpret_cast<float4*>(g_aggB)[n * 16 + c] = accB;
    if (dosum && c == 0) {
        g_dpos[n] = wsumA;
        g_dneg[n] = wsumB;
    }
}

// ---------------- layer 1: z = tanh([ap,x]@w1p+b1p | [an,x]@w1n+b1n) ---------
// Writes z as fp16 into g_zh.
__global__ __launch_bounds__(128) void layer1_kernel(
    const float4* __restrict__ x4,
    const float* __restrict__ w1p, const float* __restrict__ b1p,
    const float* __restrict__ w1n, const float* __restrict__ b1n) {
    __shared__ float sWp[128 * 32];
    __shared__ float sWn[128 * 32];
    for (int i = threadIdx.x; i < 128 * 32; i += 128) {
        sWp[i] = w1p[i];
        sWn[i] = w1n[i];
    }
    __syncthreads();

    int n = blockIdx.x * 128 + threadIdx.x;
    if (n >= NN) return;

    float invp = 1.f / fmaxf(g_dpos[n], 1e-12f);
    float invn = 1.f / fmaxf(g_dneg[n], 1e-12f);

    float aP[32], aN[32];
#pragma unroll
    for (int j = 0; j < 32; j++) { aP[j] = b1p[j]; aN[j] = b1n[j]; }

    const float4* rA = reinterpret_cast<const float4*>(g_aggA) + n * 16;
    const float4* rB = reinterpret_cast<const float4*>(g_aggB) + n * 16;
    const float4* rX = x4 + n * 16;

#pragma unroll 1
    for (int k4 = 0; k4 < 16; k4++) {
        float4 a = rA[k4];
        float4 b = rB[k4];
        float4 xv = rX[k4];
        float av[4] = { a.x * invp, a.y * invp, a.z * invp, a.w * invp };
        float bv[4] = { b.x * invn, b.y * invn, b.z * invn, b.w * invn };
        float xe[4] = { xv.x, xv.y, xv.z, xv.w };
#pragma unroll
        for (int kk = 0; kk < 4; kk++) {
            int k = k4 * 4 + kk;
            const float4* wpA = reinterpret_cast<const float4*>(sWp + k * 32);
            const float4* wpX = reinterpret_cast<const float4*>(sWp + (64 + k) * 32);
            const float4* wnA = reinterpret_cast<const float4*>(sWn + k * 32);
            const float4* wnX = reinterpret_cast<const float4*>(sWn + (64 + k) * 32);
#pragma unroll
            for (int j4 = 0; j4 < 8; j4++) {
                float4 wp = wpA[j4];
                float4 wx = wpX[j4];
                float4 wn = wnA[j4];
                float4 wq = wnX[j4];
                aP[4 * j4 + 0] += av[kk] * wp.x + xe[kk] * wx.x;
                aP[4 * j4 + 1] += av[kk] * wp.y + xe[kk] * wx.y;
                aP[4 * j4 + 2] += av[kk] * wp.z + xe[kk] * wx.z;
                aP[4 * j4 + 3] += av[kk] * wp.w + xe[kk] * wx.w;
                aN[4 * j4 + 0] += bv[kk] * wn.x + xe[kk] * wq.x;
                aN[4 * j4 + 1] += bv[kk] * wn.y + xe[kk] * wq.y;
                aN[4 * j4 + 2] += bv[kk] * wn.z + xe[kk] * wq.z;
                aN[4 * j4 + 3] += bv[kk] * wn.w + xe[kk] * wq.w;
            }
        }
    }

    // z row = [zp(32) | zn(32)] halfs
    __half2* zr = reinterpret_cast<__half2*>(g_zh + (size_t)n * 64);
#pragma unroll
    for (int t2 = 0; t2 < 16; t2++) {
        zr[t2] = __floats2half2_rn(tanha(aP[2 * t2]), tanha(aP[2 * t2 + 1]));
        zr[16 + t2] = __floats2half2_rn(tanha(aN[2 * t2]), tanha(aN[2 * t2 + 1]));
    }
}

// ---------------- layer 2 ----------------------------------------------------
// Reads z fp16; writes z2 fp32 in-place into g_aggA (row-private).
__global__ __launch_bounds__(128) void layer2_kernel(
    const float* __restrict__ w2p, const float* __restrict__ b2p,
    const float* __restrict__ w2n, const float* __restrict__ b2n) {
    __shared__ float sP[96 * 32];
    __shared__ float sN[96 * 32];
    for (int i = threadIdx.x; i < 96 * 32; i += 128) {
        sP[i] = w2p[i];
        sN[i] = w2n[i];
    }
    __syncthreads();

    int n = blockIdx.x * 128 + threadIdx.x;
    if (n >= NN) return;

    float invp = 1.f / fmaxf(g_dpos[n], 1e-12f);
    float invn = 1.f / fmaxf(g_dneg[n], 1e-12f);

    float aP[32], aN[32];
#pragma unroll
    for (int j = 0; j < 32; j++) { aP[j] = b2p[j]; aN[j] = b2n[j]; }

    const float4* rA = reinterpret_cast<const float4*>(g_aggA) + n * 16;
    const float4* rB = reinterpret_cast<const float4*>(g_aggB) + n * 16;
    const uint2*  rZ = reinterpret_cast<const uint2*>(g_zh) + n * 16;

#pragma unroll 1
    for (int k4 = 0; k4 < 8; k4++) {
        float4 A1 = rA[k4];
        float4 A3 = rA[8 + k4];
        float4 A2 = rB[k4];
        float4 A4 = rB[8 + k4];
        uint2 zpu = rZ[k4];
        uint2 znu = rZ[8 + k4];
        float2 zp0 = __half22float2(*reinterpret_cast<__half2*>(&zpu.x));
        float2 zp1 = __half22float2(*reinterpret_cast<__half2*>(&zpu.y));
        float2 zn0 = __half22float2(*reinterpret_cast<__half2*>(&znu.x));
        float2 zn1 = __half22float2(*reinterpret_cast<__half2*>(&znu.y));
        float a1[4] = { A1.x * invp, A1.y * invp, A1.z * invp, A1.w * invp };
        float a3[4] = { A3.x * invp, A3.y * invp, A3.z * invp, A3.w * invp };
        float a2[4] = { A2.x * invn, A2.y * invn, A2.z * invn, A2.w * invn };
        float a4[4] = { A4.x * invn, A4.y * invn, A4.z * invn, A4.w * invn };
        float zpv[4] = { zp0.x, zp0.y, zp1.x, zp1.y };
        float znv[4] = { zn0.x, zn0.y, zn1.x, zn1.y };
#pragma unroll
        for (int kk = 0; kk < 4; kk++) {
            int k = k4 * 4 + kk;
            const float4* p0 = reinterpret_cast<const float4*>(sP + k * 32);
            const float4* p1 = reinterpret_cast<const float4*>(sP + (32 + k) * 32);
            const float4* p2 = reinterpret_cast<const float4*>(sP + (64 + k) * 32);
            const float4* q0 = reinterpret_cast<const float4*>(sN + k * 32);
            const float4* q1 = reinterpret_cast<const float4*>(sN + (32 + k) * 32);
            const float4* q2 = reinterpret_cast<const float4*>(sN + (64 + k) * 32);
#pragma unroll
            for (int j4 = 0; j4 < 8; j4++) {
                float4 w0 = p0[j4], w1 = p1[j4], w2 = p2[j4];
                aP[4 * j4 + 0] += a1[kk] * w0.x + a2[kk] * w1.x + zpv[kk] * w2.x;
                aP[4 * j4 + 1] += a1[kk] * w0.y + a2[kk] * w1.y + zpv[kk] * w2.y;
                aP[4 * j4 + 2] += a1[kk] * w0.z + a2[kk] * w1.z + zpv[kk] * w2.z;
                aP[4 * j4 + 3] += a1[kk] * w0.w + a2[kk] * w1.w + zpv[kk] * w2.w;
                float4 v0 = q0[j4], v1 = q1[j4], v2 = q2[j4];
                aN[4 * j4 + 0] += a3[kk] * v0.x + a4[kk] * v1.x + znv[kk] * v2.x;
                aN[4 * j4 + 1] += a3[kk] * v0.y + a4[kk] * v1.y + znv[kk] * v2.y;
                aN[4 * j4 + 2] += a3[kk] * v0.z + a4[kk] * v1.z + znv[kk] * v2.z;
                aN[4 * j4 + 3] += a3[kk] * v0.w + a4[kk] * v1.w + znv[kk] * v2.w;
            }
        }
    }

    // z2 (fp32) in-place into g_aggA row n (this thread's private row)
    float4* zr = reinterpret_cast<float4*>(g_aggA) + n * 16;
#pragma unroll
    for (int j4 = 0; j4 < 8; j4++) {
        zr[j4] = make_float4(tanha(aP[4 * j4 + 0]), tanha(aP[4 * j4 + 1]),
                             tanha(aP[4 * j4 + 2]), tanha(aP[4 * j4 + 3]));
        zr[8 + j4] = make_float4(tanha(aN[4 * j4 + 0]), tanha(aN[4 * j4 + 1]),
                                 tanha(aN[4 * j4 + 2]), tanha(aN[4 * j4 + 3]));
    }
}

// ---------------- layer 3: out = tanh(z2 @ wout + bout) ----------------------
__global__ __launch_bounds__(128) void layer3_kernel(
    const float* __restrict__ wout, const float* __restrict__ bout,
    float* __restrict__ out) {
    __shared__ float sO[64 * 64];
    for (int i = threadIdx.x; i < 64 * 64; i += 128) sO[i] = wout[i];
    __syncthreads();

    int n = blockIdx.x * 128 + threadIdx.x;
    if (n >= NN) return;

    float o[64];
#pragma unroll
    for (int j = 0; j < 64; j++) o[j] = bout[j];

    const float4* rz = reinterpret_cast<const float4*>(g_aggA) + n * 16;
#pragma unroll 1
    for (int k4 = 0; k4 < 16; k4++) {
        float4 zc = rz[k4];
        float zv[4] = { zc.x, zc.y, zc.z, zc.w };
#pragma unroll
        for (int kk = 0; kk < 4; kk++) {
            const float4* wr = reinterpret_cast<const float4*>(sO + (k4 * 4 + kk) * 64);
#pragma unroll
            for (int j4 = 0; j4 < 16; j4++) {
                float4 w = wr[j4];
                o[4 * j4 + 0] += zv[kk] * w.x;
                o[4 * j4 + 1] += zv[kk] * w.y;
                o[4 * j4 + 2] += zv[kk] * w.z;
                o[4 * j4 + 3] += zv[kk] * w.w;
            }
        }
    }

    float4* orow = reinterpret_cast<float4*>(out + (size_t)n * 64);
#pragma unroll
    for (int j4 = 0; j4 < 16; j4++) {
        orow[j4] = make_float4(tanha(o[4 * j4 + 0]), tanha(o[4 * j4 + 1]),
                               tanha(o[4 * j4 + 2]), tanha(o[4 * j4 + 3]));
    }
}

// ---------------- launch -----------------------------------------------------
extern "C" void kernel_launch(void* const* d_in, const int* in_sizes, int n_in,
                              void* d_out, int out_size) {
    const int*   pei  = (const int*)d_in[0];
    const int*   nei  = (const int*)d_in[1];
    const float* pw   = (const float*)d_in[2];
    const float* nw   = (const float*)d_in[3];
    const float* x    = (const float*)d_in[4];
    const float* w1p  = (const float*)d_in[5];
    const float* b1p  = (const float*)d_in[6];
    const float* w1n  = (const float*)d_in[7];
    const float* b1n  = (const float*)d_in[8];
    const float* w2p  = (const float*)d_in[9];
    const float* b2p  = (const float*)d_in[10];
    const float* w2n  = (const float*)d_in[11];
    const float* b2n  = (const float*)d_in[12];
    const float* wout = (const float*)d_in[13];
    const float* bout = (const float*)d_in[14];
    float* out = (float*)d_out;

    const int EB = (EP + EN + 255) / 256;
    const int GB = (NN * 16 + 255) / 256;
    const int LB = (NN + 127) / 128;

    // launch #0..#4: prep + CSR build  →  launch #5 = gather #1 (ncu -s 5 target)
    prep_kernel<<<(NN * 16 + 255) / 256, 256>>>((const float4*)x);
    hist_kernel<<<EB, 256>>>(pei, nei);
    scan1_kernel<<<dim3(NBLK, 2), 1024>>>();
    scan3_kernel<<<dim3(NBLK, 2), 1024>>>();
    fill_kernel<<<EB, 256>>>(pei, nei, pw, nw);

    // Layer 1 (gather also computes the per-node weight sums)
    gather_kernel<<<GB, 256>>>(0, 0, 1);
    layer1_kernel<<<LB, 128>>>((const float4*)x, w1p, b1p, w1n, b1n);

    // Layer 2 (neg side swaps zp/zn halves in the gather), then layer 3
    gather_kernel<<<GB, 256>>>(1, 1, 0);
    layer2_kernel<<<LB, 128>>>(w2p, b2p, w2n, b2n);
    layer3_kernel<<<LB, 128>>>(wout, bout, out);

    (void)in_sizes; (void)n_in; (void)out_size;
}

// round 14
// speedup vs baseline: 1.2739x; 1.1741x over previous
#include <cuda_runtime.h>
#include <cuda_fp16.h>
#include <mma.h>
#include <cstdint>

using namespace nvcuda;

#define NN 100000
#define EP 1000000
#define EN 500000
#define NBLK ((NN + 1023) / 1024)   // 98
#define NTILES (NN / 16)            // 6250 (exact)
#define GEMMG ((NTILES + 3) / 4)    // 1563

// ---------------- scratch (device globals: no allocations allowed) ----------
// A buffers: [NN x 192] fp16 row-major. cols 0:64 = pos-agg, 64:128 = neg-agg,
// 128:192 = node features (x for layer1, z for layer2).
__device__ __align__(256) __half g_A1[NN * 192];
__device__ __align__(256) __half g_A2[NN * 192];
__device__ __align__(256) __half g_z2[NN * 64];
__device__ __align__(256) __half g_W1[192 * 64];
__device__ __align__(256) __half g_W2[192 * 64];
__device__ __align__(256) __half g_Wo[64 * 64];
__device__ __align__(256) float  g_b1[64];
__device__ __align__(256) float  g_b2[64];
__device__ __align__(256) float  g_b3[64];
// CSR build
__device__ __align__(256) int  g_pcnt[NN];
__device__ __align__(256) int  g_ncnt[NN];
__device__ __align__(256) int  g_poff[NN + 1];
__device__ __align__(256) int  g_noff[NN + 1];
__device__ __align__(256) int  g_prank[EP];
__device__ __align__(256) int  g_nrank[EN];
__device__ __align__(256) int  g_blksum[2][NBLK];
__device__ __align__(256) int2 g_pedge[EP];
__device__ __align__(256) int2 g_nedge[EN];

// ---------------- helpers ----------------------------------------------------
__device__ __forceinline__ float tanha(float x) {
    float r;
    asm("tanh.approx.f32 %0, %1;" : "=f"(r) : "f"(x));
    return r;
}

// ---------------- prep: x -> fp16 into A1 cols 128:192 + zero counters ------
__global__ void prep_kernel(const float4* __restrict__ x4) {
    int i = blockIdx.x * blockDim.x + threadIdx.x;
    if (i < NN * 16) {
        int n = i >> 4, c = i & 15;
        float4 v = x4[i];
        __half2 h0 = __floats2half2_rn(v.x, v.y);
        __half2 h1 = __floats2half2_rn(v.z, v.w);
        uint2 u;
        u.x = *reinterpret_cast<const unsigned*>(&h0);
        u.y = *reinterpret_cast<const unsigned*>(&h1);
        reinterpret_cast<uint2*>(g_A1)[n * 48 + 32 + c] = u;
    }
    if (i < NN) {
        g_pcnt[i] = 0;
        g_ncnt[i] = 0;
    }
}

// ---------------- weight folding ---------------------------------------------
// W1' (192x64): A1 = [ap | an | x].
//   col j<32 (zp):  k<64 -> w1p[k,j]; k>=128 -> w1p[k-64,j]; else 0
//   col 32+j (zn):  k>=64 -> w1n[k-64,j]; else 0
// W2' (192x64): A2 = [aggP | aggN | z], aggP=[Pzp|Pzn], aggN=[Nzn|Nzp], z=[zp|zn].
//   col j<32 (op): k<32 -> w2p[k,j]; 64<=k<96 -> w2p[k-32,j]; 128<=k<160 -> w2p[k-64,j]
//   col 32+j (on): 32<=k<64 -> w2n[k-32,j]; 96<=k<128 -> w2n[k-64,j]; k>=160 -> w2n[k-96,j]
__global__ void wprep_kernel(const float* __restrict__ w1p, const float* __restrict__ b1p,
                             const float* __restrict__ w1n, const float* __restrict__ b1n,
                             const float* __restrict__ w2p, const float* __restrict__ b2p,
                             const float* __restrict__ w2n, const float* __restrict__ b2n,
                             const float* __restrict__ wout, const float* __restrict__ bout) {
    int stride = gridDim.x * blockDim.x;
    int t = blockIdx.x * blockDim.x + threadIdx.x;
    for (int i = t; i < 192 * 64; i += stride) {
        int k = i >> 6, j = i & 63;
        float v = 0.f;
        if (j < 32) {
            if (k < 64) v = w1p[k * 32 + j];
            else if (k >= 128) v = w1p[(k - 64) * 32 + j];
        } else {
            int jj = j - 32;
            if (k >= 64) v = w1n[(k - 64) * 32 + jj];
        }
        g_W1[i] = __float2half(v);
        float u = 0.f;
        if (j < 32) {
            if (k < 32) u = w2p[k * 32 + j];
            else if (k >= 64 && k < 96) u = w2p[(k - 32) * 32 + j];
            else if (k >= 128 && k < 160) u = w2p[(k - 64) * 32 + j];
        } else {
            int jj = j - 32;
            if (k >= 32 && k < 64) u = w2n[(k - 32) * 32 + jj];
            else if (k >= 96 && k < 128) u = w2n[(k - 64) * 32 + jj];
            else if (k >= 160) u = w2n[(k - 96) * 32 + jj];
        }
        g_W2[i] = __float2half(u);
    }
    for (int i = t; i < 64 * 64; i += stride) g_Wo[i] = __float2half(wout[i]);
    for (int i = t; i < 64; i += stride) {
        g_b1[i] = (i < 32) ? b1p[i] : b1n[i - 32];
        g_b2[i] = (i < 32) ? b2p[i] : b2n[i - 32];
        g_b3[i] = bout[i];
    }
}

// ---------------- CSR build --------------------------------------------------
__global__ void hist_kernel(const int* __restrict__ pei, const int* __restrict__ nei) {
    int t = blockIdx.x * blockDim.x + threadIdx.x;
    if (t < EP) {
        int d = pei[EP + t];
        g_prank[t] = atomicAdd(&g_pcnt[d], 1);
    } else if (t < EP + EN) {
        int e = t - EP;
        int d = nei[EN + e];
        g_nrank[e] = atomicAdd(&g_ncnt[d], 1);
    }
}

__global__ void scan1_kernel() {
    __shared__ int swsum[32];
    int arr = blockIdx.y;
    const int* cnt = arr ? g_ncnt : g_pcnt;
    int* off = arr ? g_noff : g_poff;
    int tid = threadIdx.x, lane = tid & 31, wid = tid >> 5;
    int i = blockIdx.x * 1024 + tid;
    int v = (i < NN) ? cnt[i] : 0;
    int val = v;
#pragma unroll
    for (int o = 1; o < 32; o <<= 1) {
        int t2 = __shfl_up_sync(0xFFFFFFFFu, val, o);
        if (lane >= o) val += t2;
    }
    if (lane == 31) swsum[wid] = val;
    __syncthreads();
    if (wid == 0) {
        int s = swsum[lane];
#pragma unroll
        for (int o = 1; o < 32; o <<= 1) {
            int t2 = __shfl_up_sync(0xFFFFFFFFu, s, o);
            if (lane >= o) s += t2;
        }
        swsum[lane] = s;
    }
    __syncthreads();
    int woff = wid ? swsum[wid - 1] : 0;
    int incl = val + woff;
    if (i < NN) off[i] = incl - v;
    if (tid == 1023) g_blksum[arr][blockIdx.x] = incl;
}

__global__ void scan3_kernel() {
    __shared__ int s_pref;
    int arr = blockIdx.y;
    int* off = arr ? g_noff : g_poff;
    int bx = blockIdx.x;
    if (threadIdx.x < 32) {
        int lane = threadIdx.x;
        int acc = 0;
        for (int idx = lane; idx < bx; idx += 32) acc += g_blksum[arr][idx];
#pragma unroll
        for (int o = 16; o; o >>= 1) acc += __shfl_xor_sync(0xFFFFFFFFu, acc, o);
        if (lane == 0) s_pref = acc;
    }
    __syncthreads();
    int pref = s_pref;
    int i = bx * 1024 + threadIdx.x;
    if (i < NN) off[i] += pref;
    if (bx == NBLK - 1 && threadIdx.x == 0)
        off[NN] = pref + g_blksum[arr][NBLK - 1];
}

__global__ void fill_kernel(const int* __restrict__ pei, const int* __restrict__ nei,
                            const float* __restrict__ pw, const float* __restrict__ nw) {
    int t = blockIdx.x * blockDim.x + threadIdx.x;
    if (t < EP) {
        int dst = pei[EP + t];
        g_pedge[g_poff[dst] + g_prank[t]] = make_int2(pei[t], __float_as_int(pw[t]));
    } else if (t < EP + EN) {
        int e = t - EP;
        int dst = nei[EN + e];
        g_nedge[g_noff[dst] + g_nrank[e]] = make_int2(nei[e], __float_as_int(nw[e]));
    }
}

// ---------------- CSR gather -------------------------------------------------
// 16 threads/node. Reads the feature region (cols 128:192) of featA, writes
// weighted MEANS (scaled fp16) into cols 0:128 of dstA. Disjoint columns, so
// featA may equal dstA. swap: neg side reads chunk c^8 (layer-2 half swap).
__device__ __forceinline__ void h4acc(uint2 r, float w, float4& acc) {
    __half2 ha = *reinterpret_cast<__half2*>(&r.x);
    __half2 hb = *reinterpret_cast<__half2*>(&r.y);
    float2 fa = __half22float2(ha);
    float2 fb = __half22float2(hb);
    acc.x += w * fa.x; acc.y += w * fa.y;
    acc.z += w * fb.x; acc.w += w * fb.y;
}

__global__ void gather_kernel(const __half* __restrict__ featA,
                              __half* __restrict__ dstA, int swap) {
    int t = blockIdx.x * blockDim.x + threadIdx.x;
    int n = t >> 4;
    if (n >= NN) return;
    int c = t & 15;
    const uint2* feat = reinterpret_cast<const uint2*>(featA);

    float4 accA = make_float4(0.f, 0.f, 0.f, 0.f);
    float wsumA = 0.f;
    {
        int b = g_poff[n], e = g_poff[n + 1];
        int i = b;
        for (; i + 4 <= e; i += 4) {
            int2 e0 = g_pedge[i + 0];
            int2 e1 = g_pedge[i + 1];
            int2 e2 = g_pedge[i + 2];
            int2 e3 = g_pedge[i + 3];
            uint2 r0 = __ldg(&feat[e0.x * 48 + 32 + c]);
            uint2 r1 = __ldg(&feat[e1.x * 48 + 32 + c]);
            uint2 r2 = __ldg(&feat[e2.x * 48 + 32 + c]);
            uint2 r3 = __ldg(&feat[e3.x * 48 + 32 + c]);
            float w0 = __int_as_float(e0.y), w1 = __int_as_float(e1.y);
            float w2 = __int_as_float(e2.y), w3 = __int_as_float(e3.y);
            wsumA += w0 + w1 + w2 + w3;
            h4acc(r0, w0, accA);
            h4acc(r1, w1, accA);
            h4acc(r2, w2, accA);
            h4acc(r3, w3, accA);
        }
        for (; i < e; i++) {
            int2 ed = g_pedge[i];
            float w = __int_as_float(ed.y);
            uint2 r = __ldg(&feat[ed.x * 48 + 32 + c]);
            wsumA += w;
            h4acc(r, w, accA);
        }
    }

    int sc = c ^ (swap << 3);
    float4 accB = make_float4(0.f, 0.f, 0.f, 0.f);
    float wsumB = 0.f;
    {
        int b = g_noff[n], e = g_noff[n + 1];
        int i = b;
        for (; i + 4 <= e; i += 4) {
            int2 e0 = g_nedge[i + 0];
            int2 e1 = g_nedge[i + 1];
            int2 e2 = g_nedge[i + 2];
            int2 e3 = g_nedge[i + 3];
            uint2 r0 = __ldg(&feat[e0.x * 48 + 32 + sc]);
            uint2 r1 = __ldg(&feat[e1.x * 48 + 32 + sc]);
            uint2 r2 = __ldg(&feat[e2.x * 48 + 32 + sc]);
            uint2 r3 = __ldg(&feat[e3.x * 48 + 32 + sc]);
            float w0 = __int_as_float(e0.y), w1 = __int_as_float(e1.y);
            float w2 = __int_as_float(e2.y), w3 = __int_as_float(e3.y);
            wsumB += w0 + w1 + w2 + w3;
            h4acc(r0, w0, accB);
            h4acc(r1, w1, accB);
            h4acc(r2, w2, accB);
            h4acc(r3, w3, accB);
        }
        for (; i < e; i++) {
            int2 ed = g_nedge[i];
            float w = __int_as_float(ed.y);
            uint2 r = __ldg(&feat[ed.x * 48 + 32 + sc]);
            wsumB += w;
            h4acc(r, w, accB);
        }
    }

    float invA = 1.f / fmaxf(wsumA, 1e-12f);
    float invB = 1.f / fmaxf(wsumB, 1e-12f);
    __half2 a0 = __floats2half2_rn(accA.x * invA, accA.y * invA);
    __half2 a1 = __floats2half2_rn(accA.z * invA, accA.w * invA);
    __half2 b0 = __floats2half2_rn(accB.x * invB, accB.y * invB);
    __half2 b1 = __floats2half2_rn(accB.z * invB, accB.w * invB);
    uint2 ua, ub;
    ua.x = *reinterpret_cast<const unsigned*>(&a0);
    ua.y = *reinterpret_cast<const unsigned*>(&a1);
    ub.x = *reinterpret_cast<const unsigned*>(&b0);
    ub.y = *reinterpret_cast<const unsigned*>(&b1);
    reinterpret_cast<uint2*>(dstA)[n * 48 + c] = ua;
    reinterpret_cast<uint2*>(dstA)[n * 48 + 16 + c] = ub;
}

// ---------------- tensor-core GEMM + tanh epilogue ---------------------------
// C[NN,64] = tanh(A[NN,K] @ W[K,64] + bias). A,W fp16; accum fp32.
// FP32OUT: write float to outf (stride 64); else half to outh (stride out_stride).
template <int K, bool FP32OUT>
__global__ __launch_bounds__(128) void gemm_kernel(
    const __half* __restrict__ A, const __half* __restrict__ W,
    const float* __restrict__ bias,
    __half* __restrict__ outh, float* __restrict__ outf, int out_stride) {
    __shared__ __align__(32) __half sW[K * 64];
    __shared__ float sB[64];
    __shared__ __align__(32) float sC[4][16 * 64];

    int tid = threadIdx.x;
    for (int i = tid; i < K * 8; i += 128)
        reinterpret_cast<uint4*>(sW)[i] = reinterpret_cast<const uint4*>(W)[i];
    if (tid < 64) sB[tid] = bias[tid];
    __syncthreads();

    int warp = tid >> 5;
    int lane = tid & 31;
    int tile = blockIdx.x * 4 + warp;
    if (tile >= NTILES) return;

    wmma::fragment<wmma::accumulator, 16, 16, 16, float> c[4];
#pragma unroll
    for (int j = 0; j < 4; j++) wmma::fill_fragment(c[j], 0.f);

    const __half* Arow = A + (size_t)tile * 16 * K;
#pragma unroll
    for (int k0 = 0; k0 < K; k0 += 16) {
        wmma::fragment<wmma::matrix_a, 16, 16, 16, __half, wmma::row_major> a;
        wmma::load_matrix_sync(a, Arow + k0, K);
#pragma unroll
        for (int j = 0; j < 4; j++) {
            wmma::fragment<wmma::matrix_b, 16, 16, 16, __half, wmma::row_major> b;
            wmma::load_matrix_sync(b, sW + k0 * 64 + j * 16, 64);
            wmma::mma_sync(c[j], a, b, c[j]);
        }
    }

    float* stage = sC[warp];
#pragma unroll
    for (int j = 0; j < 4; j++)
        wmma::store_matrix_sync(stage + j * 16, c[j], 64, wmma::mem_row_major);
    __syncwarp();

    size_t rowbase = (size_t)tile * 16;
    if (FP32OUT) {
        for (int i = lane; i < 16 * 64; i += 32) {
            int r = i >> 6, col = i & 63;
            outf[(rowbase + r) * 64 + col] = tanha(stage[i] + sB[col]);
        }
    } else {
        for (int i = lane; i < 16 * 32; i += 32) {
            int r = i >> 5, cp = i & 31;
            float v0 = tanha(stage[r * 64 + 2 * cp] + sB[2 * cp]);
            float v1 = tanha(stage[r * 64 + 2 * cp + 1] + sB[2 * cp + 1]);
            reinterpret_cast<__half2*>(outh + (rowbase + r) * out_stride)[cp] =
                __floats2half2_rn(v0, v1);
        }
    }
}

// ---------------- launch -----------------------------------------------------
extern "C" void kernel_launch(void* const* d_in, const int* in_sizes, int n_in,
                              void* d_out, int out_size) {
    const int*   pei  = (const int*)d_in[0];
    const int*   nei  = (const int*)d_in[1];
    const float* pw   = (const float*)d_in[2];
    const float* nw   = (const float*)d_in[3];
    const float* x    = (const float*)d_in[4];
    const float* w1p  = (const float*)d_in[5];
    const float* b1p  = (const float*)d_in[6];
    const float* w1n  = (const float*)d_in[7];
    const float* b1n  = (const float*)d_in[8];
    const float* w2p  = (const float*)d_in[9];
    const float* b2p  = (const float*)d_in[10];
    const float* w2n  = (const float*)d_in[11];
    const float* b2n  = (const float*)d_in[12];
    const float* wout = (const float*)d_in[13];
    const float* bout = (const float*)d_in[14];
    float* out = (float*)d_out;

    const int EB = (EP + EN + 255) / 256;
    const int GB = (NN * 16 + 255) / 256;

    // Resolve device-global symbol addresses for kernel args (host-side, capture-safe)
    static __half* pA1 = nullptr;
    static __half* pA2 = nullptr;
    static __half* pz2 = nullptr;
    if (!pA1) {
        void* p;
        cudaGetSymbolAddress(&p, g_A1); pA1 = (__half*)p;
        cudaGetSymbolAddress(&p, g_A2); pA2 = (__half*)p;
        cudaGetSymbolAddress(&p, g_z2); pz2 = (__half*)p;
    }
    static __half* pW1 = nullptr;
    static __half* pW2 = nullptr;
    static __half* pWo = nullptr;
    static float *pb1 = nullptr, *pb2 = nullptr, *pb3 = nullptr;
    if (!pW1) {
        void* p;
        cudaGetSymbolAddress(&p, g_W1); pW1 = (__half*)p;
        cudaGetSymbolAddress(&p, g_W2); pW2 = (__half*)p;
        cudaGetSymbolAddress(&p, g_Wo); pWo = (__half*)p;
        cudaGetSymbolAddress(&p, g_b1); pb1 = (float*)p;
        cudaGetSymbolAddress(&p, g_b2); pb2 = (float*)p;
        cudaGetSymbolAddress(&p, g_b3); pb3 = (float*)p;
    }

    // prep + weight folding + CSR build
    prep_kernel<<<GB, 256>>>((const float4*)x);
    wprep_kernel<<<64, 256>>>(w1p, b1p, w1n, b1n, w2p, b2p, w2n, b2n, wout, bout);
    hist_kernel<<<EB, 256>>>(pei, nei);
    scan1_kernel<<<dim3(NBLK, 2), 1024>>>();
    scan3_kernel<<<dim3(NBLK, 2), 1024>>>();
    fill_kernel<<<EB, 256>>>(pei, nei, pw, nw);

    // Layer 1: gather x-means into A1, GEMM -> z into A2 cols 128:192
    gather_kernel<<<GB, 256>>>(pA1, pA1, 0);
    gemm_kernel<192, false><<<GEMMG, 128>>>(pA1, pW1, pb1, pA2 + 128, nullptr, 192);

    // Layer 2: gather z-means into A2 (neg swaps halves), GEMM -> z2
    gather_kernel<<<GB, 256>>>(pA2, pA2, 1);
    gemm_kernel<192, false><<<GEMMG, 128>>>(pA2, pW2, pb2, pz2, nullptr, 64);

    // Layer 3: z2 @ wout
    gemm_kernel<64, true><<<GEMMG, 128>>>(pz2, pWo, pb3, nullptr, out, 64);

    (void)in_sizes; (void)n_in; (void)out_size;
}

// round 15
// speedup vs baseline: 1.3015x; 1.0217x over previous
#include <cuda_runtime.h>
#include <cuda_fp16.h>
#include <mma.h>
#include <cstdint>

using namespace nvcuda;

#define NN 100000
#define EP 1000000
#define EN 500000
#define NBLK ((NN + 1023) / 1024)   // 98
#define FINB (2 * NBLK)             // 196 finalize blocks in fill2
#define NTILES (NN / 16)            // 6250
#define GEMMG ((NTILES + 3) / 4)    // 1563
#define PB ((NN * 16 + 255) / 256)  // 6250 prep blocks
#define WB 16                       // wprep blocks
#define EB ((EP + EN + 255) / 256)  // 5860 edge blocks

// ---------------- scratch (device globals: no allocations allowed) ----------
// A buffers: [NN x 192] fp16 row-major. cols 0:64 = pos-agg, 64:128 = neg-agg,
// 128:192 = node features (x for layer1, z for layer2).
__device__ __align__(256) __half g_A1[NN * 192];
__device__ __align__(256) __half g_A2[NN * 192];
__device__ __align__(256) __half g_z2[NN * 64];
__device__ __align__(256) __half g_W1[192 * 64];
__device__ __align__(256) __half g_W2[192 * 64];
__device__ __align__(256) __half g_Wo[64 * 64];
__device__ __align__(256) float  g_b1[64];
__device__ __align__(256) float  g_b2[64];
__device__ __align__(256) float  g_b3[64];
// CSR build. INVARIANT: g_pcnt/g_ncnt are zero at kernel_launch entry
// (zero-initialized at load; re-zeroed by fill2's finalize blocks each call).
__device__ __align__(256) int  g_pcnt[NN];
__device__ __align__(256) int  g_ncnt[NN];
__device__ __align__(256) int  g_plocal[NN];     // scan1 block-local excl offsets
__device__ __align__(256) int  g_nlocal[NN];
__device__ __align__(256) int  g_poff[NN + 1];   // finalized offsets
__device__ __align__(256) int  g_noff[NN + 1];
__device__ __align__(256) int  g_prank[EP];
__device__ __align__(256) int  g_nrank[EN];
__device__ __align__(256) int  g_blksum[2][NBLK];
__device__ __align__(256) int2 g_pedge[EP];
__device__ __align__(256) int2 g_nedge[EN];

// ---------------- helpers ----------------------------------------------------
__device__ __forceinline__ float tanha(float x) {
    float r;
    asm("tanh.approx.f32 %0, %1;" : "=f"(r) : "f"(x));
    return r;
}

// ---------------- launch #0: prep (x->fp16) + weight folding + hist ----------
__global__ void prep_all_kernel(
    const float4* __restrict__ x4,
    const float* __restrict__ w1p, const float* __restrict__ b1p,
    const float* __restrict__ w1n, const float* __restrict__ b1n,
    const float* __restrict__ w2p, const float* __restrict__ b2p,
    const float* __restrict__ w2n, const float* __restrict__ b2n,
    const float* __restrict__ wout, const float* __restrict__ bout,
    const int* __restrict__ pei, const int* __restrict__ nei) {
    int bx = blockIdx.x;
    int tid = threadIdx.x;
    if (bx < PB) {
        // x -> fp16 into A1 cols 128:192
        int i = bx * 256 + tid;
        if (i < NN * 16) {
            int n = i >> 4, c = i & 15;
            float4 v = x4[i];
            __half2 h0 = __floats2half2_rn(v.x, v.y);
            __half2 h1 = __floats2half2_rn(v.z, v.w);
            uint2 u;
            u.x = *reinterpret_cast<const unsigned*>(&h0);
            u.y = *reinterpret_cast<const unsigned*>(&h1);
            reinterpret_cast<uint2*>(g_A1)[n * 48 + 32 + c] = u;
        }
    } else if (bx < PB + WB) {
        // weight folding (see round-14 comment for the block-sparse layout)
        int t = (bx - PB) * 256 + tid;
        int stride = WB * 256;
        for (int i = t; i < 192 * 64; i += stride) {
            int k = i >> 6, j = i & 63;
            float v = 0.f;
            if (j < 32) {
                if (k < 64) v = w1p[k * 32 + j];
                else if (k >= 128) v = w1p[(k - 64) * 32 + j];
            } else {
                int jj = j - 32;
                if (k >= 64) v = w1n[(k - 64) * 32 + jj];
            }
            g_W1[i] = __float2half(v);
            float u = 0.f;
            if (j < 32) {
                if (k < 32) u = w2p[k * 32 + j];
                else if (k >= 64 && k < 96) u = w2p[(k - 32) * 32 + j];
                else if (k >= 128 && k < 160) u = w2p[(k - 64) * 32 + j];
            } else {
                int jj = j - 32;
                if (k >= 32 && k < 64) u = w2n[(k - 32) * 32 + jj];
                else if (k >= 96 && k < 128) u = w2n[(k - 64) * 32 + jj];
                else if (k >= 160) u = w2n[(k - 96) * 32 + jj];
            }
            g_W2[i] = __float2half(u);
        }
        for (int i = t; i < 64 * 64; i += stride) g_Wo[i] = __float2half(wout[i]);
        for (int i = t; i < 64; i += stride) {
            g_b1[i] = (i < 32) ? b1p[i] : b1n[i - 32];
            g_b2[i] = (i < 32) ? b2p[i] : b2n[i - 32];
            g_b3[i] = bout[i];
        }
    } else {
        // hist: counts + per-edge rank (counters are zero at entry)
        int t = (bx - PB - WB) * 256 + tid;
        if (t < EP) {
            int d = pei[EP + t];
            g_prank[t] = atomicAdd(&g_pcnt[d], 1);
        } else if (t < EP + EN) {
            int e = t - EP;
            int d = nei[EN + e];
            g_nrank[e] = atomicAdd(&g_ncnt[d], 1);
        }
    }
}

// ---------------- launch #1: per-block exclusive scan ------------------------
__global__ void scan1_kernel() {
    __shared__ int swsum[32];
    int arr = blockIdx.y;
    const int* cnt = arr ? g_ncnt : g_pcnt;
    int* loc = arr ? g_nlocal : g_plocal;
    int tid = threadIdx.x, lane = tid & 31, wid = tid >> 5;
    int i = blockIdx.x * 1024 + tid;
    int v = (i < NN) ? cnt[i] : 0;
    int val = v;
#pragma unroll
    for (int o = 1; o < 32; o <<= 1) {
        int t2 = __shfl_up_sync(0xFFFFFFFFu, val, o);
        if (lane >= o) val += t2;
    }
    if (lane == 31) swsum[wid] = val;
    __syncthreads();
    if (wid == 0) {
        int s = swsum[lane];
#pragma unroll
        for (int o = 1; o < 32; o <<= 1) {
            int t2 = __shfl_up_sync(0xFFFFFFFFu, s, o);
            if (lane >= o) s += t2;
        }
        swsum[lane] = s;
    }
    __syncthreads();
    int woff = wid ? swsum[wid - 1] : 0;
    int incl = val + woff;
    if (i < NN) loc[i] = incl - v;
    if (tid == 1023) g_blksum[arr][blockIdx.x] = incl;
}

// ---------------- launch #2: finalize offsets + fill CSR (+ re-zero cnts) ----
__global__ void fill2_kernel(const int* __restrict__ pei, const int* __restrict__ nei,
                             const float* __restrict__ pw, const float* __restrict__ nw) {
    int bx = blockIdx.x;
    int tid = threadIdx.x;
    if (bx < FINB) {
        // finalize: off = local + prefix(blksum); zero counters for next call
        int arr = bx / NBLK;
        int b = bx % NBLK;
        __shared__ int s_pref;
        if (tid < 32) {
            int acc = 0;
            for (int idx = tid; idx < b; idx += 32) acc += g_blksum[arr][idx];
#pragma unroll
            for (int o = 16; o; o >>= 1) acc += __shfl_xor_sync(0xFFFFFFFFu, acc, o);
            if (tid == 0) s_pref = acc;
        }
        __syncthreads();
        int pref = s_pref;
        const int* loc = arr ? g_nlocal : g_plocal;
        int* off = arr ? g_noff : g_poff;
        int* cnt = arr ? g_ncnt : g_pcnt;
#pragma unroll
        for (int k = 0; k < 4; k++) {
            int i = b * 1024 + k * 256 + tid;
            if (i < NN) {
                off[i] = loc[i] + pref;
                cnt[i] = 0;
            }
        }
        if (b == NBLK - 1 && tid == 0)
            off[NN] = pref + g_blksum[arr][NBLK - 1];
    } else {
        // edge fill: compute the 98-entry block prefix locally (no dependency
        // on the finalize blocks), then slot = local[dst] + pref + rank.
        __shared__ int spref[2][NBLK];
        int wid = tid >> 5, lane = tid & 31;
        if (wid < 2) {
            int carry = 0;
            for (int base = 0; base < NBLK; base += 32) {
                int idx = base + lane;
                int v = (idx < NBLK) ? g_blksum[wid][idx] : 0;
                int s = v;
#pragma unroll
                for (int o = 1; o < 32; o <<= 1) {
                    int t2 = __shfl_up_sync(0xFFFFFFFFu, s, o);
                    if (lane >= o) s += t2;
                }
                if (idx < NBLK) spref[wid][idx] = carry + s - v;
                carry += __shfl_sync(0xFFFFFFFFu, s, 31);
            }
        }
        __syncthreads();
        int t = (bx - FINB) * 256 + tid;
        if (t < EP) {
            int dst = pei[EP + t];
            int slot = g_plocal[dst] + spref[0][dst >> 10] + g_prank[t];
            g_pedge[slot] = make_int2(pei[t], __float_as_int(pw[t]));
        } else if (t < EP + EN) {
            int e = t - EP;
            int dst = nei[EN + e];
            int slot = g_nlocal[dst] + spref[1][dst >> 10] + g_nrank[e];
            g_nedge[slot] = make_int2(nei[e], __float_as_int(nw[e]));
        }
    }
}

// ---------------- CSR gather (launch #3 = ncu capture target) ----------------
// 16 threads/node; reads feature cols 128:192 of featA, writes scaled means
// (fp16) into cols 0:128 of dstA. swap: neg side reads chunk c^8.
__device__ __forceinline__ void h4acc(uint2 r, float w, float4& acc) {
    __half2 ha = *reinterpret_cast<__half2*>(&r.x);
    __half2 hb = *reinterpret_cast<__half2*>(&r.y);
    float2 fa = __half22float2(ha);
    float2 fb = __half22float2(hb);
    acc.x += w * fa.x; acc.y += w * fa.y;
    acc.z += w * fb.x; acc.w += w * fb.y;
}

__global__ void gather_kernel(const __half* __restrict__ featA,
                              __half* __restrict__ dstA, int swap) {
    int t = blockIdx.x * blockDim.x + threadIdx.x;
    int n = t >> 4;
    if (n >= NN) return;
    int c = t & 15;
    const uint2* feat = reinterpret_cast<const uint2*>(featA);

    float4 accA = make_float4(0.f, 0.f, 0.f, 0.f);
    float wsumA = 0.f;
    {
        int b = g_poff[n], e = g_poff[n + 1];
        int i = b;
        for (; i + 4 <= e; i += 4) {
            int2 e0 = g_pedge[i + 0];
            int2 e1 = g_pedge[i + 1];
            int2 e2 = g_pedge[i + 2];
            int2 e3 = g_pedge[i + 3];
            uint2 r0 = __ldg(&feat[e0.x * 48 + 32 + c]);
            uint2 r1 = __ldg(&feat[e1.x * 48 + 32 + c]);
            uint2 r2 = __ldg(&feat[e2.x * 48 + 32 + c]);
            uint2 r3 = __ldg(&feat[e3.x * 48 + 32 + c]);
            float w0 = __int_as_float(e0.y), w1 = __int_as_float(e1.y);
            float w2 = __int_as_float(e2.y), w3 = __int_as_float(e3.y);
            wsumA += w0 + w1 + w2 + w3;
            h4acc(r0, w0, accA);
            h4acc(r1, w1, accA);
            h4acc(r2, w2, accA);
            h4acc(r3, w3, accA);
        }
        for (; i < e; i++) {
            int2 ed = g_pedge[i];
            float w = __int_as_float(ed.y);
            uint2 r = __ldg(&feat[ed.x * 48 + 32 + c]);
            wsumA += w;
            h4acc(r, w, accA);
        }
    }

    int sc = c ^ (swap << 3);
    float4 accB = make_float4(0.f, 0.f, 0.f, 0.f);
    float wsumB = 0.f;
    {
        int b = g_noff[n], e = g_noff[n + 1];
        int i = b;
        for (; i + 4 <= e; i += 4) {
            int2 e0 = g_nedge[i + 0];
            int2 e1 = g_nedge[i + 1];
            int2 e2 = g_nedge[i + 2];
            int2 e3 = g_nedge[i + 3];
            uint2 r0 = __ldg(&feat[e0.x * 48 + 32 + sc]);
            uint2 r1 = __ldg(&feat[e1.x * 48 + 32 + sc]);
            uint2 r2 = __ldg(&feat[e2.x * 48 + 32 + sc]);
            uint2 r3 = __ldg(&feat[e3.x * 48 + 32 + sc]);
            float w0 = __int_as_float(e0.y), w1 = __int_as_float(e1.y);
            float w2 = __int_as_float(e2.y), w3 = __int_as_float(e3.y);
            wsumB += w0 + w1 + w2 + w3;
            h4acc(r0, w0, accB);
            h4acc(r1, w1, accB);
            h4acc(r2, w2, accB);
            h4acc(r3, w3, accB);
        }
        for (; i < e; i++) {
            int2 ed = g_nedge[i];
            float w = __int_as_float(ed.y);
            uint2 r = __ldg(&feat[ed.x * 48 + 32 + sc]);
            wsumB += w;
            h4acc(r, w, accB);
        }
    }

    float invA = 1.f / fmaxf(wsumA, 1e-12f);
    float invB = 1.f / fmaxf(wsumB, 1e-12f);
    __half2 a0 = __floats2half2_rn(accA.x * invA, accA.y * invA);
    __half2 a1 = __floats2half2_rn(accA.z * invA, accA.w * invA);
    __half2 b0 = __floats2half2_rn(accB.x * invB, accB.y * invB);
    __half2 b1 = __floats2half2_rn(accB.z * invB, accB.w * invB);
    uint2 ua, ub;
    ua.x = *reinterpret_cast<const unsigned*>(&a0);
    ua.y = *reinterpret_cast<const unsigned*>(&a1);
    ub.x = *reinterpret_cast<const unsigned*>(&b0);
    ub.y = *reinterpret_cast<const unsigned*>(&b1);
    reinterpret_cast<uint2*>(dstA)[n * 48 + c] = ua;
    reinterpret_cast<uint2*>(dstA)[n * 48 + 16 + c] = ub;
}

// ---------------- tensor-core GEMM + tanh epilogue ---------------------------
template <int K, bool FP32OUT>
__global__ __launch_bounds__(128) void gemm_kernel(
    const __half* __restrict__ A, const __half* __restrict__ W,
    const float* __restrict__ bias,
    __half* __restrict__ outh, float* __restrict__ outf, int out_stride) {
    __shared__ __align__(32) __half sW[K * 64];
    __shared__ float sB[64];
    __shared__ __align__(32) float sC[4][16 * 64];

    int tid = threadIdx.x;
    for (int i = tid; i < K * 8; i += 128)
        reinterpret_cast<uint4*>(sW)[i] = reinterpret_cast<const uint4*>(W)[i];
    if (tid < 64) sB[tid] = bias[tid];
    __syncthreads();

    int warp = tid >> 5;
    int lane = tid & 31;
    int tile = blockIdx.x * 4 + warp;
    if (tile >= NTILES) return;

    wmma::fragment<wmma::accumulator, 16, 16, 16, float> c[4];
#pragma unroll
    for (int j = 0; j < 4; j++) wmma::fill_fragment(c[j], 0.f);

    const __half* Arow = A + (size_t)tile * 16 * K;
#pragma unroll
    for (int k0 = 0; k0 < K; k0 += 16) {
        wmma::fragment<wmma::matrix_a, 16, 16, 16, __half, wmma::row_major> a;
        wmma::load_matrix_sync(a, Arow + k0, K);
#pragma unroll
        for (int j = 0; j < 4; j++) {
            wmma::fragment<wmma::matrix_b, 16, 16, 16, __half, wmma::row_major> b;
            wmma::load_matrix_sync(b, sW + k0 * 64 + j * 16, 64);
            wmma::mma_sync(c[j], a, b, c[j]);
        }
    }

    float* stage = sC[warp];
#pragma unroll
    for (int j = 0; j < 4; j++)
        wmma::store_matrix_sync(stage + j * 16, c[j], 64, wmma::mem_row_major);
    __syncwarp();

    size_t rowbase = (size_t)tile * 16;
    if (FP32OUT) {
        for (int i = lane; i < 16 * 64; i += 32) {
            int r = i >> 6, col = i & 63;
            outf[(rowbase + r) * 64 + col] = tanha(stage[i] + sB[col]);
        }
    } else {
        for (int i = lane; i < 16 * 32; i += 32) {
            int r = i >> 5, cp = i & 31;
            float v0 = tanha(stage[r * 64 + 2 * cp] + sB[2 * cp]);
            float v1 = tanha(stage[r * 64 + 2 * cp + 1] + sB[2 * cp + 1]);
            reinterpret_cast<__half2*>(outh + (rowbase + r) * out_stride)[cp] =
                __floats2half2_rn(v0, v1);
        }
    }
}

// ---------------- launch -----------------------------------------------------
extern "C" void kernel_launch(void* const* d_in, const int* in_sizes, int n_in,
                              void* d_out, int out_size) {
    const int*   pei  = (const int*)d_in[0];
    const int*   nei  = (const int*)d_in[1];
    const float* pw   = (const float*)d_in[2];
    const float* nw   = (const float*)d_in[3];
    const float* x    = (const float*)d_in[4];
    const float* w1p  = (const float*)d_in[5];
    const float* b1p  = (const float*)d_in[6];
    const float* w1n  = (const float*)d_in[7];
    const float* b1n  = (const float*)d_in[8];
    const float* w2p  = (const float*)d_in[9];
    const float* b2p  = (const float*)d_in[10];
    const float* w2n  = (const float*)d_in[11];
    const float* b2n  = (const float*)d_in[12];
    const float* wout = (const float*)d_in[13];
    const float* bout = (const float*)d_in[14];
    float* out = (float*)d_out;

    const int GB = (NN * 16 + 255) / 256;

    static __half *pA1 = nullptr, *pA2 = nullptr, *pz2 = nullptr;
    static __half *pW1 = nullptr, *pW2 = nullptr, *pWo = nullptr;
    static float *pb1 = nullptr, *pb2 = nullptr, *pb3 = nullptr;
    if (!pA1) {
        void* p;
        cudaGetSymbolAddress(&p, g_A1); pA1 = (__half*)p;
        cudaGetSymbolAddress(&p, g_A2); pA2 = (__half*)p;
        cudaGetSymbolAddress(&p, g_z2); pz2 = (__half*)p;
        cudaGetSymbolAddress(&p, g_W1); pW1 = (__half*)p;
        cudaGetSymbolAddress(&p, g_W2); pW2 = (__half*)p;
        cudaGetSymbolAddress(&p, g_Wo); pWo = (__half*)p;
        cudaGetSymbolAddress(&p, g_b1); pb1 = (float*)p;
        cudaGetSymbolAddress(&p, g_b2); pb2 = (float*)p;
        cudaGetSymbolAddress(&p, g_b3); pb3 = (float*)p;
    }

    // #0: prep + weight folding + hist (counters zero at entry by invariant)
    prep_all_kernel<<<PB + WB + EB, 256>>>((const float4*)x,
                                           w1p, b1p, w1n, b1n,
                                           w2p, b2p, w2n, b2n, wout, bout,
                                           pei, nei);
    // #1: per-block scans
    scan1_kernel<<<dim3(NBLK, 2), 1024>>>();
    // #2: finalize offsets (+ re-zero counters) and fill CSR
    fill2_kernel<<<FINB + EB, 256>>>(pei, nei, pw, nw);

    // #3: gather 1 (profiled) — x-means into A1
    gather_kernel<<<GB, 256>>>(pA1, pA1, 0);
    // #4: GEMM layer 1 -> z into A2 cols 128:192
    gemm_kernel<192, false><<<GEMMG, 128>>>(pA1, pW1, pb1, pA2 + 128, nullptr, 192);
    // #5: gather 2 (neg swaps halves) — z-means into A2
    gather_kernel<<<GB, 256>>>(pA2, pA2, 1);
    // #6: GEMM layer 2 -> z2
    gemm_kernel<192, false><<<GEMMG, 128>>>(pA2, pW2, pb2, pz2, nullptr, 64);
    // #7: GEMM layer 3 -> out
    gemm_kernel<64, true><<<GEMMG, 128>>>(pz2, pWo, pb3, nullptr, out, 64);

    (void)in_sizes; (void)n_in; (void)out_size;
}